// round 7
// baseline (speedup 1.0000x reference)
#include <cuda_runtime.h>
#include <cstdint>

#define Bq 4
#define T 128
#define D 300
#define D4 75            // D / 4 (float4 count per row)

// Scratch for projected q (rows 0..511), k (512..1023), v (1024..1535)
__device__ __align__(16) float g_qkv[3 * Bq * T * D];

// ---------------------------------------------------------------------------
// Kernel 1: batched projection GEMM (round-5 winner, unchanged).
// 32x64 tiles, 128 threads, 4x4 microtile, k-chunk 32, double-buffered.
// Grid 5 x 48 = 240 CTAs.
// ---------------------------------------------------------------------------
__global__ __launch_bounds__(128) void proj_kernel(
    const float* __restrict__ query, const float* __restrict__ key,
    const float* __restrict__ value,
    const float* __restrict__ WQ, const float* __restrict__ bQ,
    const float* __restrict__ WK, const float* __restrict__ bK)
{
    __shared__ float A_s[2][32][36];
    __shared__ float W_s[2][32][68];

    const int row0 = blockIdx.y * 32;
    const int col0 = blockIdx.x * 64;
    const int tid  = threadIdx.x;
    const int tx   = tid & 15;
    const int ty   = tid >> 4;

    const int sel = row0 >> 9;
    const float* Ap = (sel == 0) ? query : (sel == 1 ? key : value);
    const float* Wp = (sel == 0) ? WQ : WK;
    const float* bp = (sel == 0) ? bQ : bK;
    const int arow0 = row0 & 511;

    const int NC = (D + 31) / 32;
    float4 a_r[2], w_r[4];

    auto fetch = [&](int k0) {
#pragma unroll
        for (int p = 0; p < 2; p++) {
            int idx = p * 128 + tid;
            int ar = idx & 31, kk = k0 + ((idx >> 5) << 2);
            a_r[p] = (kk < D) ? *(const float4*)&Ap[(arow0 + ar) * D + kk]
                              : make_float4(0.f, 0.f, 0.f, 0.f);
        }
#pragma unroll
        for (int p = 0; p < 4; p++) {
            int idx = p * 128 + tid;
            int wr = idx & 63, kk = k0 + ((idx >> 6) << 2);
            int gc = col0 + wr;
            w_r[p] = (kk < D && gc < D) ? *(const float4*)&Wp[gc * D + kk]
                                        : make_float4(0.f, 0.f, 0.f, 0.f);
        }
    };
    auto store = [&](int buf) {
#pragma unroll
        for (int p = 0; p < 2; p++) {
            int idx = p * 128 + tid;
            int ar = idx & 31, e = (idx >> 5) << 2;
            A_s[buf][e + 0][ar] = a_r[p].x; A_s[buf][e + 1][ar] = a_r[p].y;
            A_s[buf][e + 2][ar] = a_r[p].z; A_s[buf][e + 3][ar] = a_r[p].w;
        }
#pragma unroll
        for (int p = 0; p < 4; p++) {
            int idx = p * 128 + tid;
            int wr = idx & 63, e = (idx >> 6) << 2;
            W_s[buf][e + 0][wr] = w_r[p].x; W_s[buf][e + 1][wr] = w_r[p].y;
            W_s[buf][e + 2][wr] = w_r[p].z; W_s[buf][e + 3][wr] = w_r[p].w;
        }
    };

    float acc[4][4];
#pragma unroll
    for (int r = 0; r < 4; r++)
#pragma unroll
        for (int c = 0; c < 4; c++) acc[r][c] = 0.f;

    fetch(0);
    store(0);
    __syncthreads();

    for (int ch = 0; ch < NC; ch++) {
        const int buf = ch & 1;
        if (ch + 1 < NC) fetch((ch + 1) * 32);
#pragma unroll
        for (int e = 0; e < 32; e++) {
            float4 av = *(const float4*)&A_s[buf][e][ty * 4];
            float4 wv = *(const float4*)&W_s[buf][e][tx * 4];
            float a4[4] = {av.x, av.y, av.z, av.w};
            float w4[4] = {wv.x, wv.y, wv.z, wv.w};
#pragma unroll
            for (int r = 0; r < 4; r++)
#pragma unroll
                for (int c = 0; c < 4; c++) acc[r][c] += a4[r] * w4[c];
        }
        if (ch + 1 < NC) store(1 - buf);
        __syncthreads();
    }

#pragma unroll
    for (int r = 0; r < 4; r++) {
        int gr = row0 + ty * 4 + r;
#pragma unroll
        for (int c = 0; c < 4; c++) {
            int gcol = col0 + tx * 4 + c;
            if (gcol < D) g_qkv[gr * D + gcol] = acc[r][c] + bp[gcol];
        }
    }
}

// ---------------------------------------------------------------------------
// Kernel 2: fused attention. One CTA per (b, i), 256 threads, 2 CTAs/SM
// with a 128-register budget: explicit 2-deep register pipeline over j so
// each warp keeps ~9 LDG.128 (4.6KB) in flight -> ~73KB/SM outstanding.
// ---------------------------------------------------------------------------
struct J9 {
    float4 l0, l1, l2;   // hL
    float4 r0, r1, r2;   // hR
    float4 k0, k1, k2;   // k
};

__global__ __launch_bounds__(256, 2) void attn_kernel(
    const float* __restrict__ hL, const float* __restrict__ hR,
    float* __restrict__ out)
{
    __shared__ float q_s[304];
    __shared__ float scores_s[128];
    __shared__ float attn_s[128];

    const int tid  = threadIdx.x;
    const int lane = tid & 31;
    const int w    = tid >> 5;           // 8 warps
    const int b    = blockIdx.x >> 7;
    const int i    = blockIdx.x & 127;

    const float4* qkv4 = (const float4*)g_qkv;

    // ---- load q_i (L2-hot, tiny) ----
    if (tid < D4) ((float4*)q_s)[tid] = qkv4[(b * T + i) * D4 + tid];
    __syncthreads();

    const float4* q4 = (const float4*)q_s;
    const bool has_c = (lane < D4 - 64);           // lane < 11
    const float4 qa = q4[lane];
    const float4 qb = q4[lane + 32];
    const float4 qc = has_c ? q4[lane + 64] : make_float4(0.f, 0.f, 0.f, 0.f);

    const float4* hL4 = (const float4*)hL + (size_t)(b * T + i) * T * D4;
    const float4* hRb = (const float4*)hR + ((size_t)b * T * T + i) * D4;
    const float4* k4b = qkv4 + (Bq * T + b * T) * D4;

    const int j0 = w * 16;

    auto load_j = [&](J9& s, int j) {
        const float4* hl = hL4 + (size_t)j * D4;
        const float4* hr = hRb + (size_t)j * T * D4;
        const float4* kp = k4b + j * D4;
        s.l0 = hl[lane];      s.r0 = hr[lane];      s.k0 = kp[lane];
        s.l1 = hl[lane + 32]; s.r1 = hr[lane + 32]; s.k1 = kp[lane + 32];
        if (has_c) {
            s.l2 = hl[lane + 64]; s.r2 = hr[lane + 64]; s.k2 = kp[lane + 64];
        }
    };
    auto score_j = [&](const J9& s, int j) {
        float acc = (qa.x + s.l0.x) * (s.k0.x + s.r0.x)
                  + (qa.y + s.l0.y) * (s.k0.y + s.r0.y)
                  + (qa.z + s.l0.z) * (s.k0.z + s.r0.z)
                  + (qa.w + s.l0.w) * (s.k0.w + s.r0.w)
                  + (qb.x + s.l1.x) * (s.k1.x + s.r1.x)
                  + (qb.y + s.l1.y) * (s.k1.y + s.r1.y)
                  + (qb.z + s.l1.z) * (s.k1.z + s.r1.z)
                  + (qb.w + s.l1.w) * (s.k1.w + s.r1.w);
        if (has_c) {
            acc += (qc.x + s.l2.x) * (s.k2.x + s.r2.x)
                 + (qc.y + s.l2.y) * (s.k2.y + s.r2.y)
                 + (qc.z + s.l2.z) * (s.k2.z + s.r2.z)
                 + (qc.w + s.l2.w) * (s.k2.w + s.r2.w);
        }
#pragma unroll
        for (int o = 16; o > 0; o >>= 1)
            acc += __shfl_xor_sync(0xffffffffu, acc, o);
        if (lane == 0) scores_s[j] = acc;
    };

    // ---- 2-deep register pipeline over this warp's 16 j rows ----
    {
        J9 bufA, bufB;
        load_j(bufA, j0);
#pragma unroll
        for (int jj = 0; jj < 16; jj += 2) {
            load_j(bufB, j0 + jj + 1);
            score_j(bufA, j0 + jj);
            if (jj + 2 < 16) load_j(bufA, j0 + jj + 2);
            score_j(bufB, j0 + jj + 1);
        }
    }
    __syncthreads();

    // ---- p = softmax(scores); attn = softmax(1000*p); clip is a no-op.
    // p_max = 1/sum exactly (max exp term is 1): 1000*(p-p_max) = 1000*inv*(e-1)
    if (w == 0) {
        float s0 = scores_s[lane],      s1 = scores_s[lane + 32];
        float s2 = scores_s[lane + 64], s3 = scores_s[lane + 96];
        float m = fmaxf(fmaxf(s0, s1), fmaxf(s2, s3));
#pragma unroll
        for (int o = 16; o > 0; o >>= 1)
            m = fmaxf(m, __shfl_xor_sync(0xffffffffu, m, o));
        float e0 = expf(s0 - m), e1 = expf(s1 - m);
        float e2 = expf(s2 - m), e3 = expf(s3 - m);
        float sum = e0 + e1 + e2 + e3;
#pragma unroll
        for (int o = 16; o > 0; o >>= 1)
            sum += __shfl_xor_sync(0xffffffffu, sum, o);
        float inv = 1.f / sum;
        float a0 = expf(1000.f * inv * (e0 - 1.f));
        float a1 = expf(1000.f * inv * (e1 - 1.f));
        float a2 = expf(1000.f * inv * (e2 - 1.f));
        float a3 = expf(1000.f * inv * (e3 - 1.f));
        float sum2 = a0 + a1 + a2 + a3;
#pragma unroll
        for (int o = 16; o > 0; o >>= 1)
            sum2 += __shfl_xor_sync(0xffffffffu, sum2, o);
        float inv2 = 1.f / sum2;
        attn_s[lane]      = a0 * inv2;
        attn_s[lane + 32] = a1 * inv2;
        attn_s[lane + 64] = a2 * inv2;
        attn_s[lane + 96] = a3 * inv2;
    }
    __syncthreads();

    // ---- output: out[b,i,d] = sum_j attn_j * (v[b,j,d] + hR[b,j,i,d])
    // attn is near-one-hot after x1000 sharpening: skip negligible j.
    const float* vg  = g_qkv + (size_t)(2 * Bq * T + b * T) * D;
    const float* hRs = hR + ((size_t)b * T * T + i) * D;
#pragma unroll
    for (int rep = 0; rep < 2; rep++) {
        int d = tid + rep * 256;
        if (d < D) {
            float acc = 0.f;
            for (int j = 0; j < T; j++) {
                float a = attn_s[j];
                if (a > 1e-12f)
                    acc += a * (vg[j * D + d] + hRs[(size_t)j * T * D + d]);
            }
            out[(b * T + i) * D + d] = acc;
        }
    }
}

// ---------------------------------------------------------------------------
extern "C" void kernel_launch(void* const* d_in, const int* in_sizes, int n_in,
                              void* d_out, int out_size)
{
    const float* query = (const float*)d_in[0];
    const float* key   = (const float*)d_in[1];
    const float* value = (const float*)d_in[2];
    const float* hL    = (const float*)d_in[3];
    const float* hR    = (const float*)d_in[4];
    const float* WQ    = (const float*)d_in[5];
    const float* bQ    = (const float*)d_in[6];
    const float* WK    = (const float*)d_in[7];
    const float* bK    = (const float*)d_in[8];
    float* out = (float*)d_out;

    proj_kernel<<<dim3(5, 48), 128>>>(query, key, value, WQ, bQ, WK, bK);
    attn_kernel<<<Bq * T, 256>>>(hL, hR, out);
}